// round 17
// baseline (speedup 1.0000x reference)
#include <cuda_runtime.h>

// B=2, C=32, H=80, W=240, D=64. out (B, 2C, D, H, W) fp32.
// 629 MB stores. R13 and R15 (very different shapes) both time 88.16us
// (7.13 TB/s) -> hypothesis: DRAM write wall. Final falsification probe:
// 8-d grouping, load:store ratio 0.375 -> 0.25.
//
// Each thread: one (c, h, w4), eight consecutive d (dbase..dbase+7).
// s = w0 - dbase is 4-aligned, so all 8 y-windows (floats s-7..s+3) live in
// THREE aligned float4s E=y4[q-2], C=y4[q-1], A=y4[q]; every per-dd shift
// is a compile-time lane mix. 8 LDG.128 -> 32 STG.128 per thread.

#define W4N    60
#define QCNT   9830400u     // 32*64*80*60  (c2+32 stride in float4s)
#define QD8    1228800u     // QCNT/8 threads = 4800 * 256
#define PLANE  614400u      // 32*80*240    (per-batch input floats)
#define DSTR   4800u        // 80*60: float4 stride between consecutive d

__device__ __forceinline__ float4 mix1(float4 lo, float4 hi) {  // shift -1
    return make_float4(lo.w, hi.x, hi.y, hi.z);
}
__device__ __forceinline__ float4 mix2(float4 lo, float4 hi) {  // shift -2
    return make_float4(lo.z, lo.w, hi.x, hi.y);
}
__device__ __forceinline__ float4 mix3(float4 lo, float4 hi) {  // shift -3
    return make_float4(lo.y, lo.z, lo.w, hi.x);
}

__global__ __launch_bounds__(256)
void cost_volume_kernel(const float* __restrict__ x,
                        const float* __restrict__ y,
                        float* __restrict__ out)
{
    unsigned int j = blockIdx.x * 256u + threadIdx.x;   // [0, QD8)

    // j -> (c, d8, h, w4)
    unsigned int row = j / W4N;
    unsigned int w4  = j - row * W4N;
    unsigned int h   = row % 80u;
    unsigned int t   = row / 80u;                // < 256
    unsigned int d8  = t & 7u;
    unsigned int c   = t >> 3;                   // < 32
    int w0    = (int)(w4 * 4u);
    int dbase = (int)(d8 * 8u);                  // d = dbase + dd, dd in 0..7

    unsigned int off = (c * 80u + h) * 240u;     // b=0 input row base (floats)
    unsigned int rb0 = off >> 2;                 // in float4s
    unsigned int rb1 = (off + PLANE) >> 2;

    // ── x: one aligned float4 per batch, reused by all 8 d ──
    const float4* x4 = reinterpret_cast<const float4*>(x);
    float4 xL0 = __ldg(x4 + rb0 + w4);
    float4 xL1 = __ldg(x4 + rb1 + w4);

    // ── y window: floats s-7 .. s+3  ->  float4s q-2 (E), q-1 (C), q (A),
    //    clamped to 0; any lane with true index < 0 has w < d -> masked. ──
    int q  = (w0 - dbase) >> 2;
    int qa = max(q, 0);
    int qc = max(q - 1, 0);
    int qe = max(q - 2, 0);
    const float4* y4 = reinterpret_cast<const float4*>(y);
    float4 A0 = __ldg(y4 + rb0 + qa), A1 = __ldg(y4 + rb1 + qa);
    float4 C0 = __ldg(y4 + rb0 + qc), C1 = __ldg(y4 + rb1 + qc);
    float4 E0 = __ldg(y4 + rb0 + qe), E1 = __ldg(y4 + rb1 + qe);

    unsigned int base = ((c * 64u + (unsigned)dbase) * 80u + h) * 60u + w4;
    float4* o = reinterpret_cast<float4*>(out);

    #pragma unroll
    for (int dd = 0; dd < 8; dd++) {
        int di = dbase + dd;
        bool m0 = (w0     >= di);
        bool m1 = (w0 + 1 >= di);
        bool m2 = (w0 + 2 >= di);
        bool m3 = (w0 + 3 >= di);

        float4 vL0 = xL0, vL1 = xL1;

        // right: compile-time shuffles of (E, C, A)
        float4 vR0, vR1;
        switch (dd) {
            case 0: vR0 = A0;           vR1 = A1;           break;
            case 1: vR0 = mix1(C0, A0); vR1 = mix1(C1, A1); break;
            case 2: vR0 = mix2(C0, A0); vR1 = mix2(C1, A1); break;
            case 3: vR0 = mix3(C0, A0); vR1 = mix3(C1, A1); break;
            case 4: vR0 = C0;           vR1 = C1;           break;
            case 5: vR0 = mix1(E0, C0); vR1 = mix1(E1, C1); break;
            case 6: vR0 = mix2(E0, C0); vR1 = mix2(E1, C1); break;
            default:vR0 = mix3(E0, C0); vR1 = mix3(E1, C1); break;
        }

        if (!m0) { vL0.x = 0.0f; vL1.x = 0.0f; vR0.x = 0.0f; vR1.x = 0.0f; }
        if (!m1) { vL0.y = 0.0f; vL1.y = 0.0f; vR0.y = 0.0f; vR1.y = 0.0f; }
        if (!m2) { vL0.z = 0.0f; vL1.z = 0.0f; vR0.z = 0.0f; vR1.z = 0.0f; }
        if (!m3) { vL0.w = 0.0f; vL1.w = 0.0f; vR0.w = 0.0f; vR1.w = 0.0f; }

        unsigned int jo = base + (unsigned)dd * DSTR;
        __stcs(o + jo,             vL0);   // b=0, left  (c2 = c)
        __stcs(o + jo + QCNT,      vR0);   // b=0, right (c2 = c+32)
        __stcs(o + jo + 2u * QCNT, vL1);   // b=1, left
        __stcs(o + jo + 3u * QCNT, vR1);   // b=1, right
    }
}

extern "C" void kernel_launch(void* const* d_in, const int* in_sizes, int n_in,
                              void* d_out, int out_size)
{
    const float* x = (const float*)d_in[0];
    const float* y = (const float*)d_in[1];
    float* out = (float*)d_out;

    cost_volume_kernel<<<QD8 / 256, 256>>>(x, y, out);   // 4,800 blocks
}